// round 4
// baseline (speedup 1.0000x reference)
#include <cuda_runtime.h>
#include <mma.h>
#include <cstdint>

using namespace nvcuda;

// ---------------- problem constants ----------------
#define MAX_NODES 100000
#define DIM_D 256
#define DIM_O 128

// ---------------- scratch (device globals; no runtime alloc) ------------
__device__ __align__(16) float g_agg[(size_t)MAX_NODES * DIM_D];   // 102.4 MB
__device__ __align__(16) float g_h[(size_t)MAX_NODES * DIM_O];     // 51.2 MB

// ---------------- zero agg ----------------------------------------------
__global__ void zero_kernel(float4* __restrict__ p, int n4) {
    int i = blockIdx.x * blockDim.x + threadIdx.x;
    if (i < n4) p[i] = make_float4(0.f, 0.f, 0.f, 0.f);
}

// ---------------- scatter: agg[dst] += x[src] * w ------------------------
__global__ void scatter_kernel(const float4* __restrict__ x4,
                               const int* __restrict__ mei, int E_msg,
                               const int* __restrict__ tei,
                               const float* __restrict__ tw, int E_tgt,
                               float4* __restrict__ agg4) {
    int t = blockIdx.x * blockDim.x + threadIdx.x;
    int g = t >> 6;          // edge id
    int lane = t & 63;       // float4 slot within the 256-float row
    int E = E_msg + E_tgt;
    if (g >= E) return;

    int src, dst; float w;
    if (g < E_msg) {
        src = __ldg(&mei[g]);
        dst = __ldg(&mei[E_msg + g]);
        w = 1.0f;
    } else {
        int j = g - E_msg;
        src = __ldg(&tei[E_tgt + j]);   // flipped
        dst = __ldg(&tei[j]);
        w = __ldg(&tw[j]);
    }

    float4 v = __ldg(&x4[(long)src * 64 + lane]);
    float4 r;
    r.x = v.x * w; r.y = v.y * w; r.z = v.z * w; r.w = v.w * w;

    float* p = (float*)&agg4[(long)dst * 64 + lane];
    asm volatile("red.global.add.v4.f32 [%0], {%1,%2,%3,%4};"
                 :: "l"(p), "f"(r.x), "f"(r.y), "f"(r.z), "f"(r.w)
                 : "memory");
}

// ---------------- TF32x3 tensor-core GEMM --------------------------------
// C = relu(A0@W0 [+ A1@W1] + bias), A:[M,K] rm, W:[K,128] rm, C:[M,128].
// Block 128x128, BK=32, 256 threads (8 warps as 4x2), warp tile 32x64.
// Each fp32 operand is split hi/lo in registers; 3 mmas per tile pair give
// ~fp32 accuracy at tensor-core rate.
#define BM 128
#define BN 128
#define BKT 32
#define LDA 40     // 32 + 8 pad (float4-aligned rows: 40 % 4 == 0)
#define LDB 136    // 128 + 8 pad

__global__ __launch_bounds__(256, 2)
void gemm_tf32x3(const float* __restrict__ A0, const float* __restrict__ W0,
                 const float* __restrict__ A1, const float* __restrict__ W1,
                 const float* __restrict__ bias, float* __restrict__ C,
                 int M, int K) {
    __shared__ float As[BM * LDA];          // 20.0 KB
    __shared__ float Bs[BKT * LDB];         // 17.0 KB
    __shared__ float Cs[8 * 16 * 16];       // 8 KB: per-warp 16x16 scratch

    const int tid  = threadIdx.x;
    const int wid  = tid >> 5;
    const int lane = tid & 31;
    const int m0   = blockIdx.x * BM;
    const int wm   = wid & 3;    // warp row 0..3  -> rows wm*32 .. +32
    const int wn   = wid >> 2;   // warp col 0..1  -> cols wn*64 .. +64

    wmma::fragment<wmma::accumulator, 16, 16, 8, float> acc[2][4];
    #pragma unroll
    for (int i = 0; i < 2; i++)
        #pragma unroll
        for (int j = 0; j < 4; j++) wmma::fill_fragment(acc[i][j], 0.0f);

    #pragma unroll 1
    for (int pass = 0; pass < 2; ++pass) {
        const float* A = pass ? A1 : A0;
        const float* W = pass ? W1 : W0;
        if (A == nullptr) break;

        #pragma unroll 1
        for (int kk = 0; kk < K; kk += BKT) {
            // ---- stage A tile [128 x 32] fp32 (row-major)
            #pragma unroll
            for (int it = 0; it < 4; ++it) {
                int idx = tid + it * 256;       // float4 index 0..1023
                int r  = idx >> 3;              // row 0..127
                int c4 = idx & 7;               // float4 within 32 cols
                float4 v = make_float4(0.f, 0.f, 0.f, 0.f);
                int gr = m0 + r;
                if (gr < M)
                    v = *(const float4*)&A[(long)gr * K + kk + c4 * 4];
                *(float4*)&As[r * LDA + c4 * 4] = v;
            }
            // ---- stage B tile [32 x 128] fp32 (row-major)
            #pragma unroll
            for (int it = 0; it < 4; ++it) {
                int idx = tid + it * 256;
                int r  = idx >> 5;              // row 0..31
                int c4 = idx & 31;              // float4 within 128 cols
                *(float4*)&Bs[r * LDB + c4 * 4] =
                    *(const float4*)&W[(long)(kk + r) * 128 + c4 * 4];
            }
            __syncthreads();

            #pragma unroll
            for (int kc = 0; kc < BKT / 8; ++kc) {
                // ---- B fragments, split hi/lo
                wmma::fragment<wmma::matrix_b, 16, 16, 8,
                               wmma::precision::tf32, wmma::row_major> b_hi[4], b_lo[4];
                #pragma unroll
                for (int ni = 0; ni < 4; ++ni) {
                    wmma::load_matrix_sync(b_hi[ni],
                        &Bs[(kc * 8) * LDB + wn * 64 + ni * 16], LDB);
                    #pragma unroll
                    for (int e = 0; e < b_hi[ni].num_elements; ++e) {
                        float v  = b_hi[ni].x[e];
                        float hi = wmma::__float_to_tf32(v);
                        b_hi[ni].x[e] = hi;
                        b_lo[ni].x[e] = wmma::__float_to_tf32(v - hi);
                    }
                }
                // ---- A fragments, split hi/lo, then 3-term mma
                #pragma unroll
                for (int mi = 0; mi < 2; ++mi) {
                    wmma::fragment<wmma::matrix_a, 16, 16, 8,
                                   wmma::precision::tf32, wmma::row_major> a_hi, a_lo;
                    wmma::load_matrix_sync(a_hi,
                        &As[(wm * 32 + mi * 16) * LDA + kc * 8], LDA);
                    #pragma unroll
                    for (int e = 0; e < a_hi.num_elements; ++e) {
                        float v  = a_hi.x[e];
                        float hi = wmma::__float_to_tf32(v);
                        a_hi.x[e] = hi;
                        a_lo.x[e] = wmma::__float_to_tf32(v - hi);
                    }
                    #pragma unroll
                    for (int ni = 0; ni < 4; ++ni) {
                        wmma::mma_sync(acc[mi][ni], a_lo, b_hi[ni], acc[mi][ni]);
                        wmma::mma_sync(acc[mi][ni], a_hi, b_lo[ni], acc[mi][ni]);
                        wmma::mma_sync(acc[mi][ni], a_hi, b_hi[ni], acc[mi][ni]);
                    }
                }
            }
            __syncthreads();
        }
    }

    // ---- epilogue: per-warp 16x16 staging, bias + relu, vector stores
    float* cw = &Cs[wid * 256];
    #pragma unroll
    for (int mi = 0; mi < 2; ++mi) {
        #pragma unroll
        for (int ni = 0; ni < 4; ++ni) {
            wmma::store_matrix_sync(cw, acc[mi][ni], 16, wmma::mem_row_major);
            __syncwarp();
            int r  = lane >> 1;            // 0..15
            int c  = (lane & 1) * 8;       // 0 or 8
            int gr = m0 + wm * 32 + mi * 16 + r;
            int gc = wn * 64 + ni * 16 + c;
            if (gr < M) {
                float4 v0, v1;
                v0.x = fmaxf(cw[r * 16 + c + 0] + bias[gc + 0], 0.f);
                v0.y = fmaxf(cw[r * 16 + c + 1] + bias[gc + 1], 0.f);
                v0.z = fmaxf(cw[r * 16 + c + 2] + bias[gc + 2], 0.f);
                v0.w = fmaxf(cw[r * 16 + c + 3] + bias[gc + 3], 0.f);
                v1.x = fmaxf(cw[r * 16 + c + 4] + bias[gc + 4], 0.f);
                v1.y = fmaxf(cw[r * 16 + c + 5] + bias[gc + 5], 0.f);
                v1.z = fmaxf(cw[r * 16 + c + 6] + bias[gc + 6], 0.f);
                v1.w = fmaxf(cw[r * 16 + c + 7] + bias[gc + 7], 0.f);
                *(float4*)&C[(long)gr * 128 + gc]     = v0;
                *(float4*)&C[(long)gr * 128 + gc + 4] = v1;
            }
            __syncwarp();
        }
    }
}

// ---------------- launch --------------------------------------------------
extern "C" void kernel_launch(void* const* d_in, const int* in_sizes, int n_in,
                              void* d_out, int out_size) {
    const float* x      = (const float*)d_in[0];
    const int*   mei    = (const int*)d_in[1];
    const int*   tei    = (const int*)d_in[2];
    const float* tw     = (const float*)d_in[3];
    const float* W_rel  = (const float*)d_in[4];
    const float* b_rel  = (const float*)d_in[5];
    const float* W_root = (const float*)d_in[6];
    const float* W_mu   = (const float*)d_in[7];
    const float* b_mu   = (const float*)d_in[8];
    float* out = (float*)d_out;

    int N     = in_sizes[0] / DIM_D;       // 100000
    int E_msg = in_sizes[1] / 2;           // 1,600,000
    int E_tgt = in_sizes[2] / 2;           // 10,000

    float* agg; float* h;
    cudaGetSymbolAddress((void**)&agg, g_agg);
    cudaGetSymbolAddress((void**)&h, g_h);

    // 1) zero agg
    {
        int n4 = N * (DIM_D / 4);
        int threads = 256;
        int blocks = (n4 + threads - 1) / threads;
        zero_kernel<<<blocks, threads>>>((float4*)agg, n4);
    }

    // 2) scatter-aggregate (message edges + flipped target edges)
    {
        int E = E_msg + E_tgt;
        long total = (long)E * 64;
        int threads = 256;
        int blocks = (int)((total + threads - 1) / threads);
        scatter_kernel<<<blocks, threads>>>((const float4*)x, mei, E_msg,
                                            tei, tw, E_tgt, (float4*)agg);
    }

    // 3) h = relu(agg @ W_rel + x @ W_root + b_rel)   [tensor cores, tf32x3]
    {
        int blocks = (N + BM - 1) / BM;
        gemm_tf32x3<<<blocks, 256>>>(agg, W_rel, x, W_root, b_rel, h,
                                     N, DIM_D);
    }

    // 4) out = relu(h @ W_mu + b_mu)   (eval-mode rrelu is identity on relu output)
    {
        int blocks = (N + BM - 1) / BM;
        gemm_tf32x3<<<blocks, 256>>>(h, W_mu, nullptr, nullptr, b_mu, out,
                                     N, DIM_O);
    }

    // 5) second output: target_edge_weights appended after the [N,128] tensor
    long main_elems = (long)N * DIM_O;
    if ((long)out_size >= main_elems + E_tgt) {
        cudaMemcpyAsync(out + main_elems, tw, (size_t)E_tgt * sizeof(float),
                        cudaMemcpyDeviceToDevice);
    }
}